// round 6
// baseline (speedup 1.0000x reference)
#include <cuda_runtime.h>

#define TT 2048
#define BB 4096
#define HH 10

// K = 2*log2(e): tanh(z) = 1 - 2*r,  r = rcp(ex2(K*z) + 1)
#define KTANH 2.8853900817779268f

// Phase-A -> Phase-B scratch: A_b[j] = K*(a_b[j] + rowsum(Whh2[j,:])), padded +8 rows
__device__ float g_a[(BB + 8) * HH];
// Phase-B -> FC scratch: r_b[j]
__device__ float g_r[BB * HH];

__device__ __forceinline__ float ex2f(float a) {
    float e; asm("ex2.approx.f32 %0, %1;" : "=f"(e) : "f"(a)); return e;
}
__device__ __forceinline__ float rcpf(float a) {
    float r; asm("rcp.approx.f32 %0, %1;" : "=f"(r) : "f"(a)); return r;
}

// ---------------- Phase A: layer-1 time recurrence (r-space), shfl exchange.
// 10 warps/CTA, 3 groups of 10 lanes per warp, 2 chains per group => 60 seq/CTA.
__global__ __launch_bounds__(320, 1) void rnnA_kernel(
    const float* __restrict__ x,
    const float* __restrict__ Wih1, const float* __restrict__ Whh1,
    const float* __restrict__ bih1, const float* __restrict__ bhh1,
    const float* __restrict__ Wih2, const float* __restrict__ Whh2,
    const float* __restrict__ bih2, const float* __restrict__ bhh2)
{
    const int warp = threadIdx.x >> 5;
    const int lane = threadIdx.x & 31;
    const int g = lane / 10;          // 3 = dummy group (lanes 30,31)
    const int j = lane - g * 10;
    const int gbase = g * 10;

    const int gg = (g < 3) ? g : 0;
    const int base = (blockIdx.x * 10 + warp) * 6 + gg * 2;
    const int s0q = min(base, BB - 1);
    const int s1q = min(base + 1, BB - 1);

    // Folded layer-1 weights: acc = C1 + wi0'*x0 + wi1'*x1 + sum_k W1p[k]*r_k
    float W1p[HH];
    float rowsum1 = 0.f;
#pragma unroll
    for (int k = 0; k < HH; k++) {
        const float w = Whh1[j * HH + k];
        rowsum1 += w;
        W1p[k] = -2.0f * KTANH * w;
    }
    const float C1   = KTANH * (bih1[j] + bhh1[j] + rowsum1);
    const float wi0p = KTANH * Wih1[j * 2 + 0];
    const float wi1p = KTANH * Wih1[j * 2 + 1];

    float v0 = 0.5f, v1 = 0.5f;   // r for h = 0

    const float4* xq0 = reinterpret_cast<const float4*>(x) + (size_t)s0q * (TT / 2);
    const float4* xq1 = reinterpret_cast<const float4*>(x) + (size_t)s1q * (TT / 2);

    float4 cur0[4], cur1[4];
#pragma unroll
    for (int i = 0; i < 4; i++) { cur0[i] = xq0[i]; cur1[i] = xq1[i]; }

    for (int tl = 0; tl < TT / 8; tl++) {
        const int nb = min(tl + 1, TT / 8 - 1) * 4;
        float4 nxt0[4], nxt1[4];
#pragma unroll
        for (int i = 0; i < 4; i++) { nxt0[i] = xq0[nb + i]; nxt1[i] = xq1[nb + i]; }

#pragma unroll
        for (int s = 0; s < 8; s++) {
            const float4 q0 = cur0[s >> 1];
            const float4 q1 = cur1[s >> 1];
            const float xa0 = (s & 1) ? q0.z : q0.x;
            const float xb0 = (s & 1) ? q0.w : q0.y;
            const float xa1 = (s & 1) ? q1.z : q1.x;
            const float xb1 = (s & 1) ? q1.w : q1.y;

            float r0[HH], r1[HH];
#pragma unroll
            for (int k = 0; k < HH; k++) {
                r0[k] = __shfl_sync(0xFFFFFFFFu, v0, (gbase + k) & 31);
                r1[k] = __shfl_sync(0xFFFFFFFFu, v1, (gbase + k) & 31);
            }

            // chain 0: 4 accumulators
            float a0 = fmaf(wi0p, xa0, C1);
            float a1 = wi1p * xb0;
            float a2 = W1p[0] * r0[0];
            float a3 = W1p[1] * r0[1];
            // chain 1
            float b0 = fmaf(wi0p, xa1, C1);
            float b1 = wi1p * xb1;
            float b2 = W1p[0] * r1[0];
            float b3 = W1p[1] * r1[1];
#pragma unroll
            for (int k = 2; k < HH; k += 4) {
                a0 = fmaf(W1p[k],     r0[k],     a0);
                a1 = fmaf(W1p[k + 1], r0[k + 1], a1);
                a2 = fmaf(W1p[k + 2], r0[k + 2], a2);
                a3 = fmaf(W1p[k + 3], r0[k + 3], a3);
                b0 = fmaf(W1p[k],     r1[k],     b0);
                b1 = fmaf(W1p[k + 1], r1[k + 1], b1);
                b2 = fmaf(W1p[k + 2], r1[k + 2], b2);
                b3 = fmaf(W1p[k + 3], r1[k + 3], b3);
            }
            v0 = rcpf(ex2f((a0 + a1) + (a2 + a3)) + 1.0f);
            v1 = rcpf(ex2f((b0 + b1) + (b2 + b3)) + 1.0f);
        }
#pragma unroll
        for (int i = 0; i < 4; i++) { cur0[i] = nxt0[i]; cur1[i] = nxt1[i]; }
    }

    // Epilogue: A_b[j] = C2 + sum_k W2p[k]*r_k  (projection of y1last through Wih2,
    // with layer-2 biases, both rowsums, and the K scale folded in)
    float W2p[HH];
    float rs2 = 0.f;
#pragma unroll
    for (int k = 0; k < HH; k++) {
        const float wi = Wih2[j * HH + k];
        rs2 += wi + Whh2[j * HH + k];
        W2p[k] = -2.0f * KTANH * wi;
    }
    const float C2 = KTANH * (bih2[j] + bhh2[j] + rs2);

    float r0[HH], r1[HH];
#pragma unroll
    for (int k = 0; k < HH; k++) {
        r0[k] = __shfl_sync(0xFFFFFFFFu, v0, (gbase + k) & 31);
        r1[k] = __shfl_sync(0xFFFFFFFFu, v1, (gbase + k) & 31);
    }
    float A0 = C2, A1 = C2;
#pragma unroll
    for (int k = 0; k < HH; k++) {
        A0 = fmaf(W2p[k], r0[k], A0);
        A1 = fmaf(W2p[k], r1[k], A1);
    }
    if (g < 3) {
        if (base < BB)     g_a[(size_t)base * HH + j]       = A0;
        if (base + 1 < BB) g_a[(size_t)(base + 1) * HH + j] = A1;
    }
}

// ---------------- Phase B: serial batch-axis recurrence in r-space. Single warp.
// acc_b = A_b + sum_k V[k]*rho_k ;  rho_b = rcp(ex2(acc_b)+1) ; store rho_b.
__global__ void rnnB_kernel(const float* __restrict__ Whh2)
{
    const int lane = threadIdx.x;
    const int j = lane % HH;

    float V[HH];
#pragma unroll
    for (int k = 0; k < HH; k++) V[k] = -2.0f * KTANH * Whh2[j * HH + k];

    // depth-8 prefetch ring over padded g_a
    const float* ap = g_a + j;
    float pre[8];
#pragma unroll
    for (int i = 0; i < 8; i++) pre[i] = ap[i * HH];

    float* rp = g_r + j;
    float v = 0.5f;   // rho for g_{-1} = 0

    for (int tb = 0; tb < BB / 8; tb++) {
        const float* apn = ap + (tb * 8 + 8) * HH;
#pragma unroll
        for (int s = 0; s < 8; s++) {
            const float av = pre[s];
            pre[s] = apn[s * HH];

            float h0 = __shfl_sync(0xFFFFFFFFu, v, 0);
            float h1 = __shfl_sync(0xFFFFFFFFu, v, 1);
            float h2 = __shfl_sync(0xFFFFFFFFu, v, 2);
            float h3 = __shfl_sync(0xFFFFFFFFu, v, 3);
            float h4 = __shfl_sync(0xFFFFFFFFu, v, 4);
            float h5 = __shfl_sync(0xFFFFFFFFu, v, 5);
            float h6 = __shfl_sync(0xFFFFFFFFu, v, 6);
            float h7 = __shfl_sync(0xFFFFFFFFu, v, 7);
            float h8 = __shfl_sync(0xFFFFFFFFu, v, 8);
            float h9 = __shfl_sync(0xFFFFFFFFu, v, 9);

            float a0 = fmaf(V[0], h0, av);
            float a1 = V[1] * h1;
            float a2 = V[2] * h2;
            float a3 = V[3] * h3;
            a0 = fmaf(V[4], h4, a0);
            a1 = fmaf(V[5], h5, a1);
            a2 = fmaf(V[6], h6, a2);
            a3 = fmaf(V[7], h7, a3);
            a0 = fmaf(V[8], h8, a0);
            a1 = fmaf(V[9], h9, a1);

            v = rcpf(ex2f((a0 + a2) + (a1 + a3)) + 1.0f);

            if (lane < HH) rp[(tb * 8 + s) * HH] = v;   // off critical path
        }
    }
}

// ---------------- Kernel C: FC over all b in parallel from stored rho.
__global__ void fc_kernel(const float* __restrict__ Wfc,
                          const float* __restrict__ bfc,
                          float* __restrict__ out)
{
    const int t = blockIdx.x * blockDim.x + threadIdx.x;
    if (t >= BB * 4) return;
    const int i = t & 3;
    const int b = t >> 2;
    const float* r = g_r + (size_t)b * HH;
    float o = bfc[i];
#pragma unroll
    for (int k = 0; k < HH; k++)
        o = fmaf(Wfc[i * HH + k], fmaf(-2.0f, r[k], 1.0f), o);
    out[t] = o;
}

extern "C" void kernel_launch(void* const* d_in, const int* in_sizes, int n_in,
                              void* d_out, int out_size) {
    const float* x    = (const float*)d_in[0];
    const float* Wih1 = (const float*)d_in[1];
    const float* Whh1 = (const float*)d_in[2];
    const float* bih1 = (const float*)d_in[3];
    const float* bhh1 = (const float*)d_in[4];
    const float* Wih2 = (const float*)d_in[5];
    const float* Whh2 = (const float*)d_in[6];
    const float* bih2 = (const float*)d_in[7];
    const float* bhh2 = (const float*)d_in[8];
    const float* Wfc  = (const float*)d_in[9];
    const float* bfc  = (const float*)d_in[10];

    dim3 gridA((BB + 59) / 60);
    rnnA_kernel<<<gridA, 320>>>(x, Wih1, Whh1, bih1, bhh1,
                                Wih2, Whh2, bih2, bhh2);
    rnnB_kernel<<<1, 32>>>(Whh2);
    fc_kernel<<<(BB * 4 + 255) / 256, 256>>>(Wfc, bfc, (float*)d_out);
}

// round 7
// speedup vs baseline: 1.1071x; 1.1071x over previous
#include <cuda_runtime.h>

#define TT 2048
#define BB 4096
#define HH 10

// K = 2*log2(e): tanh(z) = 1 - 2*r,  r = rcp(ex2(K*z) + 1)
#define KTANH 2.8853900817779268f

// Phase-A -> Phase-B scratch: A_b[j] (K-scaled, rowsum-folded), padded +8 rows
__device__ float g_a[(BB + 8) * HH];
// Phase-B -> FC scratch: r_b[j]
__device__ float g_r[BB * HH];

__device__ __forceinline__ float ex2f(float a) {
    float e; asm("ex2.approx.f32 %0, %1;" : "=f"(e) : "f"(a)); return e;
}
__device__ __forceinline__ float rcpf(float a) {
    float r; asm("rcp.approx.f32 %0, %1;" : "=f"(r) : "f"(a)); return r;
}

// ---------------- Phase A: layer-1 time recurrence in r-space, smem exchange.
// 10 warps/CTA; per warp 3 groups of 10 lanes, 2 chains/group => 60 seqs/CTA.
__global__ __launch_bounds__(320, 1) void rnnA_kernel(
    const float* __restrict__ x,
    const float* __restrict__ Wih1, const float* __restrict__ Whh1,
    const float* __restrict__ bih1, const float* __restrict__ bhh1,
    const float* __restrict__ Wih2, const float* __restrict__ Whh2,
    const float* __restrict__ bih2, const float* __restrict__ bhh2)
{
    // [parity][warp][group(4: 3 real + 1 dummy)][5 x float4] ; float4 = (r0,r1) pairs
    __shared__ float4 buf[2][10][4][5];

    const int warp = threadIdx.x >> 5;
    const int lane = threadIdx.x & 31;
    const int g = lane / 10;          // 3 = dummy group (lanes 30,31)
    const int j = lane - g * 10;

    const int gg = (g < 3) ? g : 0;
    const int base = (blockIdx.x * 10 + warp) * 6 + gg * 2;
    const int s0q = min(base, BB - 1);
    const int s1q = min(base + 1, BB - 1);

    // Folded layer-1 weights (r-space): z = C1 + wi0p*x0 + wi1p*x1 + sum W1p[k]*r_k
    float W1p[HH];
    float rowsum1 = 0.f;
#pragma unroll
    for (int k = 0; k < HH; k++) {
        const float w = Whh1[j * HH + k];
        rowsum1 += w;
        W1p[k] = -2.0f * KTANH * w;
    }
    const float C1   = KTANH * (bih1[j] + bhh1[j] + rowsum1);
    const float wi0p = KTANH * Wih1[j * 2 + 0];
    const float wi1p = KTANH * Wih1[j * 2 + 1];

    // Replicated r-state for both chains
    float h0[HH], h1[HH];
#pragma unroll
    for (int k = 0; k < HH; k++) { h0[k] = 0.5f; h1[k] = 0.5f; }   // r of h=0

    const float4* xq0 = reinterpret_cast<const float4*>(x) + (size_t)s0q * (TT / 2);
    const float4* xq1 = reinterpret_cast<const float4*>(x) + (size_t)s1q * (TT / 2);

    float4 cur0[4], cur1[4];
#pragma unroll
    for (int i = 0; i < 4; i++) { cur0[i] = xq0[i]; cur1[i] = xq1[i]; }

    for (int tl = 0; tl < TT / 8; tl++) {
        const int nb = min(tl + 1, TT / 8 - 1) * 4;
        float4 nxt0[4], nxt1[4];
#pragma unroll
        for (int i = 0; i < 4; i++) { nxt0[i] = xq0[nb + i]; nxt1[i] = xq1[nb + i]; }

#pragma unroll
        for (int s = 0; s < 8; s++) {
            const int p = s & 1;
            const float4 q0 = cur0[s >> 1];
            const float4 q1 = cur1[s >> 1];
            const float xa0 = (s & 1) ? q0.z : q0.x;
            const float xb0 = (s & 1) ? q0.w : q0.y;
            const float xa1 = (s & 1) ? q1.z : q1.x;
            const float xb1 = (s & 1) ? q1.w : q1.y;

            // chain 0: 4 accumulators
            float a0 = fmaf(wi0p, xa0, C1);
            float a1 = wi1p * xb0;
            float a2 = W1p[0] * h0[0];
            float a3 = W1p[1] * h0[1];
            // chain 1
            float b0 = fmaf(wi0p, xa1, C1);
            float b1 = wi1p * xb1;
            float b2 = W1p[0] * h1[0];
            float b3 = W1p[1] * h1[1];
#pragma unroll
            for (int k = 2; k < HH; k += 4) {
                a0 = fmaf(W1p[k],     h0[k],     a0);
                a1 = fmaf(W1p[k + 1], h0[k + 1], a1);
                a2 = fmaf(W1p[k + 2], h0[k + 2], a2);
                a3 = fmaf(W1p[k + 3], h0[k + 3], a3);
                b0 = fmaf(W1p[k],     h1[k],     b0);
                b1 = fmaf(W1p[k + 1], h1[k + 1], b1);
                b2 = fmaf(W1p[k + 2], h1[k + 2], b2);
                b3 = fmaf(W1p[k + 3], h1[k + 3], b3);
            }
            const float v0 = rcpf(ex2f((a0 + a1) + (a2 + a3)) + 1.0f);
            const float v1 = rcpf(ex2f((b0 + b1) + (b2 + b3)) + 1.0f);

            // exchange: pack (v0,v1) per j, broadcast-read 5 float4
            float2* slot = reinterpret_cast<float2*>(&buf[p][warp][g][0]);
            slot[j] = make_float2(v0, v1);
            __syncwarp();
#pragma unroll
            for (int k2 = 0; k2 < 5; k2++) {
                const float4 q = buf[p][warp][g][k2];
                h0[2 * k2]     = q.x;  h1[2 * k2]     = q.y;
                h0[2 * k2 + 1] = q.z;  h1[2 * k2 + 1] = q.w;
            }
        }
#pragma unroll
        for (int i = 0; i < 4; i++) { cur0[i] = nxt0[i]; cur1[i] = nxt1[i]; }
    }

    // Epilogue: A_b[j] = C2 + sum_k W2p[k]*r_k  (Wih2 projection + folded biases/rowsums)
    float W2p[HH];
    float rs2 = 0.f;
#pragma unroll
    for (int k = 0; k < HH; k++) {
        const float wi = Wih2[j * HH + k];
        rs2 += wi + Whh2[j * HH + k];
        W2p[k] = -2.0f * KTANH * wi;
    }
    const float C2 = KTANH * (bih2[j] + bhh2[j] + rs2);

    float A0 = C2, A1 = C2;
#pragma unroll
    for (int k = 0; k < HH; k++) {
        A0 = fmaf(W2p[k], h0[k], A0);
        A1 = fmaf(W2p[k], h1[k], A1);
    }
    if (g < 3) {
        if (base < BB)     g_a[(size_t)base * HH + j]       = A0;
        if (base + 1 < BB) g_a[(size_t)(base + 1) * HH + j] = A1;
    }
}

// ---------------- Phase B: serial batch-axis recurrence in r-space. Single warp,
// smem-broadcast exchange (cheap vs SHFL's ~8cyc/instr issue cost).
__global__ void rnnB_kernel(const float* __restrict__ Whh2)
{
    __shared__ float sh[2][12];

    const int lane = threadIdx.x;
    const int j = lane % HH;

    float V[HH];
#pragma unroll
    for (int k = 0; k < HH; k++) V[k] = -2.0f * KTANH * Whh2[j * HH + k];

    // depth-8 prefetch ring over padded g_a
    const float* ap = g_a + j;
    float pre[8];
#pragma unroll
    for (int i = 0; i < 8; i++) pre[i] = ap[i * HH];

    float* rp = g_r + j;
    float v = 0.5f;   // r of g_{-1} = 0

    for (int tb = 0; tb < BB / 8; tb++) {
        const float* apn = ap + (tb * 8 + 8) * HH;
#pragma unroll
        for (int s = 0; s < 8; s++) {
            const int p = s & 1;
            const float av = pre[s];
            pre[s] = apn[s * HH];

            if (lane < HH) sh[p][lane] = v;
            __syncwarp();
            const float4 A = *reinterpret_cast<const float4*>(&sh[p][0]);
            const float4 Bq = *reinterpret_cast<const float4*>(&sh[p][4]);
            const float2 C = *reinterpret_cast<const float2*>(&sh[p][8]);

            float a0 = fmaf(V[0], A.x, av);
            float a1 = V[1] * A.y;
            float a2 = V[2] * A.z;
            float a3 = V[3] * A.w;
            a0 = fmaf(V[4], Bq.x, a0);
            a1 = fmaf(V[5], Bq.y, a1);
            a2 = fmaf(V[6], Bq.z, a2);
            a3 = fmaf(V[7], Bq.w, a3);
            a0 = fmaf(V[8], C.x, a0);
            a1 = fmaf(V[9], C.y, a1);

            v = rcpf(ex2f((a0 + a2) + (a1 + a3)) + 1.0f);

            if (lane < HH) rp[(tb * 8 + s) * HH] = v;   // off critical path
        }
    }
}

// ---------------- Kernel C: FC over all b in parallel from stored r.
__global__ void fc_kernel(const float* __restrict__ Wfc,
                          const float* __restrict__ bfc,
                          float* __restrict__ out)
{
    const int t = blockIdx.x * blockDim.x + threadIdx.x;
    if (t >= BB * 4) return;
    const int i = t & 3;
    const int b = t >> 2;
    const float* r = g_r + (size_t)b * HH;
    float o = bfc[i];
#pragma unroll
    for (int k = 0; k < HH; k++)
        o = fmaf(Wfc[i * HH + k], fmaf(-2.0f, r[k], 1.0f), o);
    out[t] = o;
}

extern "C" void kernel_launch(void* const* d_in, const int* in_sizes, int n_in,
                              void* d_out, int out_size) {
    const float* x    = (const float*)d_in[0];
    const float* Wih1 = (const float*)d_in[1];
    const float* Whh1 = (const float*)d_in[2];
    const float* bih1 = (const float*)d_in[3];
    const float* bhh1 = (const float*)d_in[4];
    const float* Wih2 = (const float*)d_in[5];
    const float* Whh2 = (const float*)d_in[6];
    const float* bih2 = (const float*)d_in[7];
    const float* bhh2 = (const float*)d_in[8];
    const float* Wfc  = (const float*)d_in[9];
    const float* bfc  = (const float*)d_in[10];

    dim3 gridA((BB + 59) / 60);
    rnnA_kernel<<<gridA, 320>>>(x, Wih1, Whh1, bih1, bhh1,
                                Wih2, Whh2, bih2, bhh2);
    rnnB_kernel<<<1, 32>>>(Whh2);
    fc_kernel<<<(BB * 4 + 255) / 256, 256>>>(Wfc, bfc, (float*)d_out);
}